// round 4
// baseline (speedup 1.0000x reference)
#include <cuda_runtime.h>
#include <cuda_bf16.h>
#include <cstdint>

#define NN 100000
#define DD 64
#define EE 800000
#define BM 112          // GEMM block rows (keeps static smem < 48KB)

// Scratch (static device globals — allocation-free per harness rules)
// rel 0: dd (dst=drug), 1: gd (dst=drug), 2: gg (dst=gene), 3: dg (dst=gene)
__device__ float g_agg[4][(size_t)NN * DD];   // raw-feature aggregation per relation
__device__ int   g_deg[4 * NN];               // per-relation in-degree

__device__ __forceinline__ unsigned long long ffma2(unsigned long long a,
                                                    unsigned long long b,
                                                    unsigned long long c) {
    unsigned long long d;
    asm("fma.rn.f32x2 %0, %1, %2, %3;" : "=l"(d) : "l"(a), "l"(b), "l"(c));
    return d;
}

// ---------------------------------------------------------------------------
// Kernel 1: zero agg buffers + degree counters
// ---------------------------------------------------------------------------
__global__ __launch_bounds__(256) void zero_kernel() {
    int i = blockIdx.x * blockDim.x + threadIdx.x;
    const int AGG4 = 4 * NN * DD / 4;   // 6.4M float4
    float4* a4 = (float4*)&g_agg[0][0];
    if (i < AGG4) a4[i] = make_float4(0.f, 0.f, 0.f, 0.f);
    if (i < 4 * NN / 4) ((int4*)g_deg)[i] = make_int4(0, 0, 0, 0);
}

// ---------------------------------------------------------------------------
// Kernel 2: merged scatter — all 4 relations in one launch (grid.y = rel).
// 16 lanes per edge: agg[rel][dst] += x[src] (red.v4), lane 0 bumps degree.
// ---------------------------------------------------------------------------
struct ScatArgs { const float* X[4]; const int* src[4]; const int* dst[4]; };

__global__ __launch_bounds__(256) void scatter_kernel(ScatArgs a, int e_cnt) {
    int rel = blockIdx.y;
    int gt = blockIdx.x * blockDim.x + threadIdx.x;
    int e = gt >> 4;
    if (e >= e_cnt) return;
    int l = gt & 15;

    int s = a.src[rel][e];
    int d = a.dst[rel][e];

    const float4* __restrict__ X4 = (const float4*)a.X[rel];
    float4 v = X4[(size_t)s * 16 + l];

    float* addr = &g_agg[rel][(size_t)d * DD + l * 4];
    asm volatile("red.global.add.v4.f32 [%0], {%1, %2, %3, %4};"
                 :: "l"(addr), "f"(v.x), "f"(v.y), "f"(v.z), "f"(v.w)
                 : "memory");
    if (l == 0) atomicAdd(&g_deg[rel * NN + d], 1);
}

// ---------------------------------------------------------------------------
// Kernel 3: fused projection
// out[type] = relu( (agg_r0/deg_r0) @ W_r0 + (agg_r1/deg_r1) @ W_r1 + bias )
// grid.y = dst type (0 = drug: rels 0,1 ; 1 = gene: rels 2,3)
// Block tile 112x64, thread tile 7 rows x 4 strided cols {tc, tc+16, tc+32, tc+48}.
// Conflict-free smem: Xs/Wt stored as float2[..][33] (pad 1 pair).
// ---------------------------------------------------------------------------
struct ProjArgs { const float* W[4]; const float* bias; float* out; };

__global__ __launch_bounds__(256, 2) void proj_fused_kernel(ProjArgs args) {
    __shared__ float2 Xs[BM][33];    // Xs[m][k2] = (x[m][2k2], x[m][2k2+1]); 29568 B
    __shared__ float2 Wt[DD][33];    // Wt[n][k2] = (W[2k2][n], W[2k2+1][n]); 16896 B

    int tid = threadIdx.x;
    int tc = tid & 15;               // output cols: tc + 16*c, c in 0..3
    int tr = tid >> 4;               // rows: tr*7 .. tr*7+6
    int row0 = blockIdx.x * BM;
    int grp = blockIdx.y;            // 0 = drug, 1 = gene

    unsigned long long acc[7][4];
#pragma unroll
    for (int i = 0; i < 7; i++)
#pragma unroll
        for (int c = 0; c < 4; c++) acc[i][c] = 0ull;

#pragma unroll
    for (int chunk = 0; chunk < 2; chunk++) {
        int rel = grp * 2 + chunk;
        const float* __restrict__ agg = g_agg[rel];
        const int* __restrict__ deg = g_deg + rel * NN;
        const float4* __restrict__ W4 = (const float4*)args.W[rel];

        __syncthreads();   // protect previous chunk's smem reads

        // load X tile (scaled by 1/deg): 112 rows x 16 float4 = 1792 float4
#pragma unroll
        for (int j = 0; j < 7; j++) {
            int idx = tid + j * 256;
            int m = idx >> 4;
            int q = idx & 15;
            int r = row0 + m;
            float4 v = make_float4(0.f, 0.f, 0.f, 0.f);
            float sc = 0.f;
            if (r < NN) {
                v = ((const float4*)agg)[(size_t)r * 16 + q];
                int dg = deg[r];
                sc = 1.0f / (float)(dg > 1 ? dg : 1);
            }
            Xs[m][q * 2]     = make_float2(v.x * sc, v.y * sc);
            Xs[m][q * 2 + 1] = make_float2(v.z * sc, v.w * sc);
        }
        // load W transposed into pair layout: Wt[n][k2] holds (W[2k2][n], W[2k2+1][n])
#pragma unroll
        for (int j = 0; j < 4; j++) {
            int idx = tid + j * 256;       // float4 index over 1024
            int k = idx >> 4;
            int n4 = (idx & 15) * 4;
            float4 w = ((const float4*)W4)[idx];
            // scalar scatter: float element (k & 1) of Wt[n][k>>1]
            float* wt = (float*)&Wt[0][0];
            int base = (k >> 1) * 2 + (k & 1);   // float offset within row pair array
            wt[(n4 + 0) * 66 + base] = w.x;
            wt[(n4 + 1) * 66 + base] = w.y;
            wt[(n4 + 2) * 66 + base] = w.z;
            wt[(n4 + 3) * 66 + base] = w.w;
        }
        __syncthreads();

        const unsigned long long* xrow =
            (const unsigned long long*)&Xs[tr * 7][0];
        const unsigned long long* wbase = (const unsigned long long*)&Wt[0][0];
#pragma unroll 8
        for (int k2 = 0; k2 < 32; k2++) {
            unsigned long long w2[4];
#pragma unroll
            for (int c = 0; c < 4; c++)
                w2[c] = wbase[(tc + 16 * c) * 33 + k2];
#pragma unroll
            for (int i = 0; i < 7; i++) {
                unsigned long long x2 = xrow[i * 33 + k2];
#pragma unroll
                for (int c = 0; c < 4; c++)
                    acc[i][c] = ffma2(x2, w2[c], acc[i][c]);
            }
        }
    }

    // epilogue: horizontal add of even/odd partials, bias, relu, store
    float bv[4];
#pragma unroll
    for (int c = 0; c < 4; c++) bv[c] = args.bias[tc + 16 * c];
    float* out = args.out + (size_t)grp * NN * DD;
#pragma unroll
    for (int i = 0; i < 7; i++) {
        int r = row0 + tr * 7 + i;
        if (r >= NN) break;
#pragma unroll
        for (int c = 0; c < 4; c++) {
            float2 p = *(float2*)&acc[i][c];
            out[(size_t)r * DD + tc + 16 * c] = fmaxf(p.x + p.y + bv[c], 0.f);
        }
    }
}

// ---------------------------------------------------------------------------
// Launch
// ---------------------------------------------------------------------------
extern "C" void kernel_launch(void* const* d_in, const int* in_sizes, int n_in,
                              void* d_out, int out_size) {
    const float* x_drug = (const float*)d_in[0];
    const float* x_gene = (const float*)d_in[1];
    const float* W_dd   = (const float*)d_in[2];
    const float* W_dg   = (const float*)d_in[3];
    const float* W_gd   = (const float*)d_in[4];
    const float* W_gg   = (const float*)d_in[5];
    const float* bias   = (const float*)d_in[6];
    const int* src_dd = (const int*)d_in[7];
    const int* dst_dd = (const int*)d_in[8];
    const int* src_dg = (const int*)d_in[9];
    const int* dst_dg = (const int*)d_in[10];
    const int* src_gd = (const int*)d_in[11];
    const int* dst_gd = (const int*)d_in[12];
    const int* src_gg = (const int*)d_in[13];
    const int* dst_gg = (const int*)d_in[14];
    float* out = (float*)d_out;    // [2, N, D]: out[0]=drug, out[1]=gene

    // 1) zero agg + degree
    {
        int total = 4 * NN * DD / 4;    // 6.4M float4
        zero_kernel<<<(total + 255) / 256, 256>>>();
    }

    // 2) merged scatter: all 4 relations concurrently
    {
        ScatArgs a;
        a.X[0] = x_drug; a.src[0] = src_dd; a.dst[0] = dst_dd;
        a.X[1] = x_gene; a.src[1] = src_gd; a.dst[1] = dst_gd;
        a.X[2] = x_gene; a.src[2] = src_gg; a.dst[2] = dst_gg;
        a.X[3] = x_drug; a.src[3] = src_dg; a.dst[3] = dst_dg;
        dim3 grid(((EE * 16) + 255) / 256, 4);   // (50000, 4)
        scatter_kernel<<<grid, 256>>>(a, EE);
    }

    // 3) fused projection: scale + GEMM + sum(rel) + bias + relu
    {
        ProjArgs args;
        args.W[0] = W_dd; args.W[1] = W_gd; args.W[2] = W_gg; args.W[3] = W_dg;
        args.bias = bias; args.out = out;
        dim3 grid((NN + BM - 1) / BM, 2);
        proj_fused_kernel<<<grid, 256>>>(args);
    }
}

// round 5
// speedup vs baseline: 2.0615x; 2.0615x over previous
#include <cuda_runtime.h>
#include <cuda_bf16.h>
#include <cstdint>

#define NN 100000
#define DD 64
#define EE 800000
#define BM 112          // GEMM block rows (keeps static smem < 48KB)

// Scratch (static device globals — allocation-free per harness rules)
// rel 0: dd (dst=drug), 1: gd (dst=drug), 2: gg (dst=gene), 3: dg (dst=gene)
__device__ float g_agg[4][(size_t)NN * DD];   // raw-feature aggregation per relation
__device__ int   g_deg[4 * NN];               // per-relation in-degree

__device__ __forceinline__ unsigned long long ffma2(unsigned long long a,
                                                    unsigned long long b,
                                                    unsigned long long c) {
    unsigned long long d;
    asm("fma.rn.f32x2 %0, %1, %2, %3;" : "=l"(d) : "l"(a), "l"(b), "l"(c));
    return d;
}

// ---------------------------------------------------------------------------
// Kernel 1: zero agg buffers + degree counters
// ---------------------------------------------------------------------------
__global__ __launch_bounds__(256) void zero_kernel() {
    int i = blockIdx.x * blockDim.x + threadIdx.x;
    const int AGG4 = 4 * NN * DD / 4;   // 6.4M float4
    float4* a4 = (float4*)&g_agg[0][0];
    if (i < AGG4) a4[i] = make_float4(0.f, 0.f, 0.f, 0.f);
    if (i < 4 * NN / 4) ((int4*)g_deg)[i] = make_int4(0, 0, 0, 0);
}

// ---------------------------------------------------------------------------
// Kernel 2: scatter raw features + degree count, one relation per launch
// (sequential launches keep the per-relation working set L2-resident).
// 4 lanes per edge; each lane does 4 independent LDG.128 + REDG.128 (MLP=4).
// ---------------------------------------------------------------------------
__global__ __launch_bounds__(256) void scatter_kernel(const float* __restrict__ X,
                                                      const int* __restrict__ src,
                                                      const int* __restrict__ dst,
                                                      int rel, int e_cnt) {
    int gt = blockIdx.x * blockDim.x + threadIdx.x;
    int e = gt >> 2;
    if (e >= e_cnt) return;
    int l = gt & 3;                    // lane covers float4s l*4 .. l*4+3

    int s = src[e];
    int d = dst[e];

    const float4* __restrict__ X4 = (const float4*)X;
    float4 v0 = X4[(size_t)s * 16 + l * 4 + 0];
    float4 v1 = X4[(size_t)s * 16 + l * 4 + 1];
    float4 v2 = X4[(size_t)s * 16 + l * 4 + 2];
    float4 v3 = X4[(size_t)s * 16 + l * 4 + 3];

    float* base = &g_agg[rel][(size_t)d * DD + l * 16];
    asm volatile("red.global.add.v4.f32 [%0], {%1, %2, %3, %4};"
                 :: "l"(base + 0), "f"(v0.x), "f"(v0.y), "f"(v0.z), "f"(v0.w) : "memory");
    asm volatile("red.global.add.v4.f32 [%0], {%1, %2, %3, %4};"
                 :: "l"(base + 4), "f"(v1.x), "f"(v1.y), "f"(v1.z), "f"(v1.w) : "memory");
    asm volatile("red.global.add.v4.f32 [%0], {%1, %2, %3, %4};"
                 :: "l"(base + 8), "f"(v2.x), "f"(v2.y), "f"(v2.z), "f"(v2.w) : "memory");
    asm volatile("red.global.add.v4.f32 [%0], {%1, %2, %3, %4};"
                 :: "l"(base + 12), "f"(v3.x), "f"(v3.y), "f"(v3.z), "f"(v3.w) : "memory");
    if (l == 0) atomicAdd(&g_deg[rel * NN + d], 1);
}

// ---------------------------------------------------------------------------
// Kernel 3: fused projection
// out[type] = relu( (agg_r0/deg_r0) @ W_r0 + (agg_r1/deg_r1) @ W_r1 + bias )
// grid.y = dst type (0 = drug: rels 0,1 ; 1 = gene: rels 2,3)
// Block tile 112x64, thread tile 7 rows x 4 strided cols {tc, tc+16, tc+32, tc+48}.
// Conflict-free smem: Xs/Wt stored as float2[..][33] (pad 1 pair).
// ---------------------------------------------------------------------------
struct ProjArgs { const float* W[4]; const float* bias; float* out; };

__global__ __launch_bounds__(256, 2) void proj_fused_kernel(ProjArgs args) {
    __shared__ float2 Xs[BM][33];    // Xs[m][k2] = (x[m][2k2], x[m][2k2+1])
    __shared__ float2 Wt[DD][33];    // Wt[n][k2] = (W[2k2][n], W[2k2+1][n])

    int tid = threadIdx.x;
    int tc = tid & 15;               // output cols: tc + 16*c, c in 0..3
    int tr = tid >> 4;               // rows: tr*7 .. tr*7+6
    int row0 = blockIdx.x * BM;
    int grp = blockIdx.y;            // 0 = drug, 1 = gene

    unsigned long long acc[7][4];
#pragma unroll
    for (int i = 0; i < 7; i++)
#pragma unroll
        for (int c = 0; c < 4; c++) acc[i][c] = 0ull;

#pragma unroll
    for (int chunk = 0; chunk < 2; chunk++) {
        int rel = grp * 2 + chunk;
        const float* __restrict__ agg = g_agg[rel];
        const int* __restrict__ deg = g_deg + rel * NN;
        const float4* __restrict__ W4 = (const float4*)args.W[rel];

        __syncthreads();   // protect previous chunk's smem reads

        // load X tile (scaled by 1/deg): 112 rows x 16 float4 = 1792 float4
#pragma unroll
        for (int j = 0; j < 7; j++) {
            int idx = tid + j * 256;
            int m = idx >> 4;
            int q = idx & 15;
            int r = row0 + m;
            float4 v = make_float4(0.f, 0.f, 0.f, 0.f);
            float sc = 0.f;
            if (r < NN) {
                v = ((const float4*)agg)[(size_t)r * 16 + q];
                int dg = deg[r];
                sc = 1.0f / (float)(dg > 1 ? dg : 1);
            }
            Xs[m][q * 2]     = make_float2(v.x * sc, v.y * sc);
            Xs[m][q * 2 + 1] = make_float2(v.z * sc, v.w * sc);
        }
        // load W transposed into pair layout: Wt[n][k2] holds (W[2k2][n], W[2k2+1][n])
#pragma unroll
        for (int j = 0; j < 4; j++) {
            int idx = tid + j * 256;       // float4 index over 1024
            int k = idx >> 4;
            int n4 = (idx & 15) * 4;
            float4 w = ((const float4*)W4)[idx];
            float* wt = (float*)&Wt[0][0];
            int base = (k >> 1) * 2 + (k & 1);   // float offset within row pair
            wt[(n4 + 0) * 66 + base] = w.x;
            wt[(n4 + 1) * 66 + base] = w.y;
            wt[(n4 + 2) * 66 + base] = w.z;
            wt[(n4 + 3) * 66 + base] = w.w;
        }
        __syncthreads();

        const unsigned long long* xrow =
            (const unsigned long long*)&Xs[tr * 7][0];
        const unsigned long long* wbase = (const unsigned long long*)&Wt[0][0];
#pragma unroll 8
        for (int k2 = 0; k2 < 32; k2++) {
            unsigned long long w2[4];
#pragma unroll
            for (int c = 0; c < 4; c++)
                w2[c] = wbase[(tc + 16 * c) * 33 + k2];
#pragma unroll
            for (int i = 0; i < 7; i++) {
                unsigned long long x2 = xrow[i * 33 + k2];
#pragma unroll
                for (int c = 0; c < 4; c++)
                    acc[i][c] = ffma2(x2, w2[c], acc[i][c]);
            }
        }
    }

    // epilogue: horizontal add of even/odd partials, bias, relu, store
    float bv[4];
#pragma unroll
    for (int c = 0; c < 4; c++) bv[c] = args.bias[tc + 16 * c];
    float* out = args.out + (size_t)grp * NN * DD;
#pragma unroll
    for (int i = 0; i < 7; i++) {
        int r = row0 + tr * 7 + i;
        if (r >= NN) break;
#pragma unroll
        for (int c = 0; c < 4; c++) {
            float2 p = *(float2*)&acc[i][c];
            out[(size_t)r * DD + tc + 16 * c] = fmaxf(p.x + p.y + bv[c], 0.f);
        }
    }
}

// ---------------------------------------------------------------------------
// Launch
// ---------------------------------------------------------------------------
extern "C" void kernel_launch(void* const* d_in, const int* in_sizes, int n_in,
                              void* d_out, int out_size) {
    const float* x_drug = (const float*)d_in[0];
    const float* x_gene = (const float*)d_in[1];
    const float* W_dd   = (const float*)d_in[2];
    const float* W_dg   = (const float*)d_in[3];
    const float* W_gd   = (const float*)d_in[4];
    const float* W_gg   = (const float*)d_in[5];
    const float* bias   = (const float*)d_in[6];
    const int* src_dd = (const int*)d_in[7];
    const int* dst_dd = (const int*)d_in[8];
    const int* src_dg = (const int*)d_in[9];
    const int* dst_dg = (const int*)d_in[10];
    const int* src_gd = (const int*)d_in[11];
    const int* dst_gd = (const int*)d_in[12];
    const int* src_gg = (const int*)d_in[13];
    const int* dst_gg = (const int*)d_in[14];
    float* out = (float*)d_out;    // [2, N, D]: out[0]=drug, out[1]=gene

    // 1) zero agg + degree
    {
        int total = 4 * NN * DD / 4;    // 6.4M float4
        zero_kernel<<<(total + 255) / 256, 256>>>();
    }

    // 2) scatter raw features (+degree), sequential per relation for L2 residency
    {
        int blocks = ((EE * 4) + 255) / 256;   // 12500
        scatter_kernel<<<blocks, 256>>>(x_drug, src_dd, dst_dd, 0, EE);
        scatter_kernel<<<blocks, 256>>>(x_gene, src_gd, dst_gd, 1, EE);
        scatter_kernel<<<blocks, 256>>>(x_gene, src_gg, dst_gg, 2, EE);
        scatter_kernel<<<blocks, 256>>>(x_drug, src_dg, dst_dg, 3, EE);
    }

    // 3) fused projection: scale + GEMM + sum(rel) + bias + relu
    {
        ProjArgs args;
        args.W[0] = W_dd; args.W[1] = W_gd; args.W[2] = W_gg; args.W[3] = W_dg;
        args.bias = bias; args.out = out;
        dim3 grid((NN + BM - 1) / BM, 2);
        proj_fused_kernel<<<grid, 256>>>(args);
    }
}

// round 8
// speedup vs baseline: 2.4242x; 1.1760x over previous
#include <cuda_runtime.h>
#include <cuda_bf16.h>
#include <cstdint>

#define NN 100000
#define DD 64
#define EE 800000
#define BM 112
#define NB 400000            // total buckets = 4 rels * NN
#define SCAN_BLKS 391        // ceil(400000 / 1024), 1024 elems per block

// Scratch (static device globals — allocation-free per harness rules)
// rel 0: dd (dst=drug, src x_drug), 1: gd (dst=drug, src x_gene),
//     2: gg (dst=gene, src x_gene), 3: dg (dst=gene, src x_drug)
__device__ float g_agg[4][(size_t)NN * DD];   // pre-scaled aggregation per relation
__device__ int   g_deg[NB];                   // per-bucket in-degree
__device__ int   g_start[NB];                 // exclusive-scan bucket starts
__device__ int   g_cur[NB];                   // placement cursors
__device__ int   g_eidx[4 * EE];              // src node id per edge, bucketed by dst
__device__ int   g_bsum[512];                 // scan block sums (padded)
__device__ int   g_boff[512];                 // scan block offsets

__device__ __forceinline__ unsigned long long ffma2(unsigned long long a,
                                                    unsigned long long b,
                                                    unsigned long long c) {
    unsigned long long d;
    asm("fma.rn.f32x2 %0, %1, %2, %3;" : "=l"(d) : "l"(a), "l"(b), "l"(c));
    return d;
}

// ---------------------------------------------------------------------------
// 1) zero degree counters
// ---------------------------------------------------------------------------
__global__ __launch_bounds__(256) void zero_deg_kernel() {
    int i = blockIdx.x * blockDim.x + threadIdx.x;
    if (i < NB / 4) ((int4*)g_deg)[i] = make_int4(0, 0, 0, 0);
}

// ---------------------------------------------------------------------------
// 2) degree count, all relations (grid.y = rel)
// ---------------------------------------------------------------------------
struct EdgeArgs { const int* src[4]; const int* dst[4]; };

__global__ __launch_bounds__(256) void count_kernel(EdgeArgs a, int e_cnt) {
    int rel = blockIdx.y;
    int e = blockIdx.x * blockDim.x + threadIdx.x;
    if (e < e_cnt) atomicAdd(&g_deg[rel * NN + a.dst[rel][e]], 1);
}

// ---------------------------------------------------------------------------
// 3) scan phase 1: 512 threads, 2 elements each (1024 per block).
//    Per-thread pair-sum -> Hillis-Steele over 512 -> expand to low/high.
// ---------------------------------------------------------------------------
__global__ __launch_bounds__(512) void scan1_kernel() {
    __shared__ int buf[2][512];
    int tid = threadIdx.x;
    int base = blockIdx.x * 1024 + tid * 2;
    int v0 = (base < NB) ? g_deg[base] : 0;
    int v1 = (base + 1 < NB) ? g_deg[base + 1] : 0;
    int pair = v0 + v1;
    buf[0][tid] = pair;
    __syncthreads();
    int pa = 0;
    for (int off = 1; off < 512; off <<= 1) {
        int t = buf[pa][tid];
        if (tid >= off) t += buf[pa][tid - off];
        buf[pa ^ 1][tid] = t;
        __syncthreads();
        pa ^= 1;
    }
    int incl_pair = buf[pa][tid];          // inclusive over pair-sums
    int excl_pair = incl_pair - pair;      // exclusive over pair-sums
    if (base < NB)     g_start[base]     = excl_pair;
    if (base + 1 < NB) g_start[base + 1] = excl_pair + v0;
    if (tid == 511) g_bsum[blockIdx.x] = incl_pair;
}

// ---------------------------------------------------------------------------
// 4) scan phase 2: single 512-thread block scans the 391 block sums
// ---------------------------------------------------------------------------
__global__ __launch_bounds__(512) void scan2_kernel() {
    __shared__ int buf[2][512];
    int tid = threadIdx.x;
    int v = (tid < SCAN_BLKS) ? g_bsum[tid] : 0;
    buf[0][tid] = v;
    __syncthreads();
    int pa = 0;
    for (int off = 1; off < 512; off <<= 1) {
        int t = buf[pa][tid];
        if (tid >= off) t += buf[pa][tid - off];
        buf[pa ^ 1][tid] = t;
        __syncthreads();
        pa ^= 1;
    }
    if (tid < SCAN_BLKS) g_boff[tid] = buf[pa][tid] - v;   // exclusive
}

// ---------------------------------------------------------------------------
// 5) scan phase 3: apply block offsets, init cursors (512 thr, 2 elems each)
// ---------------------------------------------------------------------------
__global__ __launch_bounds__(512) void scan3_kernel() {
    int off = g_boff[blockIdx.x];
    int base = blockIdx.x * 1024 + threadIdx.x * 2;
#pragma unroll
    for (int u = 0; u < 2; u++) {
        int i = base + u;
        if (i < NB) {
            int v = g_start[i] + off;
            g_start[i] = v;
            g_cur[i] = v;
        }
    }
}

// ---------------------------------------------------------------------------
// 6) place src ids into dst buckets (grid.y = rel)
// ---------------------------------------------------------------------------
__global__ __launch_bounds__(256) void place_kernel(EdgeArgs a, int e_cnt) {
    int rel = blockIdx.y;
    int e = blockIdx.x * blockDim.x + threadIdx.x;
    if (e >= e_cnt) return;
    int s = a.src[rel][e];
    int d = a.dst[rel][e];
    int pos = atomicAdd(&g_cur[rel * NN + d], 1);
    g_eidx[pos] = s;
}

// ---------------------------------------------------------------------------
// 7) gather-aggregate: one warp per (rel, dst node). No atomics, single write.
//    g_agg[rel][node] = (1/max(deg,1)) * sum_{src in bucket} x[src]
// ---------------------------------------------------------------------------
struct GatherArgs { const float* X[4]; };

__global__ __launch_bounds__(256) void gather_kernel(GatherArgs ga) {
    int rel = blockIdx.y;
    int node = blockIdx.x * 8 + (threadIdx.x >> 5);   // 8 warps per block
    if (node >= NN) return;
    int lane = threadIdx.x & 31;

    int b = rel * NN + node;
    int start = g_start[b];
    int cnt = g_deg[b];

    const float2* __restrict__ X2 = (const float2*)ga.X[rel];
    float2 acc = make_float2(0.f, 0.f);

    int j = 0;
    for (; j + 4 <= cnt; j += 4) {
        int id = (lane < 4) ? g_eidx[start + j + lane] : 0;
        int s0 = __shfl_sync(0xffffffffu, id, 0);
        int s1 = __shfl_sync(0xffffffffu, id, 1);
        int s2 = __shfl_sync(0xffffffffu, id, 2);
        int s3 = __shfl_sync(0xffffffffu, id, 3);
        float2 a0 = X2[(size_t)s0 * 32 + lane];
        float2 a1 = X2[(size_t)s1 * 32 + lane];
        float2 a2 = X2[(size_t)s2 * 32 + lane];
        float2 a3 = X2[(size_t)s3 * 32 + lane];
        acc.x += (a0.x + a1.x) + (a2.x + a3.x);
        acc.y += (a0.y + a1.y) + (a2.y + a3.y);
    }
    for (; j < cnt; j++) {
        int s = g_eidx[start + j];           // uniform address -> broadcast
        float2 a0 = X2[(size_t)s * 32 + lane];
        acc.x += a0.x;
        acc.y += a0.y;
    }

    float inv = 1.0f / (float)(cnt > 1 ? cnt : 1);
    acc.x *= inv; acc.y *= inv;
    ((float2*)g_agg[rel])[(size_t)node * 32 + lane] = acc;
}

// ---------------------------------------------------------------------------
// 8) fused projection: out[type] = relu(agg_r0 @ W_r0 + agg_r1 @ W_r1 + bias)
//    grid.y = dst type. 128 threads, block tile 112x64, thread tile 7x8
//    (cols tc + 8*c). Conflict-free pair-layout smem [..][33].
// ---------------------------------------------------------------------------
struct ProjArgs { const float* W[4]; const float* bias; float* out; };

__global__ __launch_bounds__(128, 2) void proj_fused_kernel(ProjArgs args) {
    __shared__ float2 Xs[BM][33];    // Xs[m][k2] = (x[m][2k2], x[m][2k2+1])
    __shared__ float2 Wt[DD][33];    // Wt[n][k2] = (W[2k2][n], W[2k2+1][n])

    int tid = threadIdx.x;
    int tc = tid & 7;                // output cols: tc + 8*c, c in 0..7
    int tr = tid >> 3;               // rows: tr*7 .. tr*7+6 (tr in 0..15)
    int row0 = blockIdx.x * BM;
    int grp = blockIdx.y;            // 0 = drug, 1 = gene

    unsigned long long acc[7][8];
#pragma unroll
    for (int i = 0; i < 7; i++)
#pragma unroll
        for (int c = 0; c < 8; c++) acc[i][c] = 0ull;

#pragma unroll
    for (int chunk = 0; chunk < 2; chunk++) {
        int rel = grp * 2 + chunk;
        const float4* __restrict__ agg4 = (const float4*)g_agg[rel];
        const float4* __restrict__ W4 = (const float4*)args.W[rel];

        __syncthreads();   // protect previous chunk's smem reads

        // load X tile: 112 rows x 16 float4 = 1792 float4, 128 threads
#pragma unroll
        for (int j = 0; j < 14; j++) {
            int idx = tid + j * 128;
            int m = idx >> 4;
            int q = idx & 15;
            int r = row0 + m;
            float4 v = make_float4(0.f, 0.f, 0.f, 0.f);
            if (r < NN) v = agg4[(size_t)r * 16 + q];
            Xs[m][q * 2]     = make_float2(v.x, v.y);
            Xs[m][q * 2 + 1] = make_float2(v.z, v.w);
        }
        // load W transposed into pair layout
#pragma unroll
        for (int j = 0; j < 8; j++) {
            int idx = tid + j * 128;       // float4 index over 1024
            int k = idx >> 4;
            int n4 = (idx & 15) * 4;
            float4 w = W4[idx];
            float* wt = (float*)&Wt[0][0];
            int base = (k >> 1) * 2 + (k & 1);
            wt[(n4 + 0) * 66 + base] = w.x;
            wt[(n4 + 1) * 66 + base] = w.y;
            wt[(n4 + 2) * 66 + base] = w.z;
            wt[(n4 + 3) * 66 + base] = w.w;
        }
        __syncthreads();

        const unsigned long long* xrow =
            (const unsigned long long*)&Xs[tr * 7][0];
        const unsigned long long* wbase = (const unsigned long long*)&Wt[0][0];
#pragma unroll 4
        for (int k2 = 0; k2 < 32; k2++) {
            unsigned long long w2[8];
#pragma unroll
            for (int c = 0; c < 8; c++)
                w2[c] = wbase[(tc + 8 * c) * 33 + k2];
#pragma unroll
            for (int i = 0; i < 7; i++) {
                unsigned long long x2 = xrow[i * 33 + k2];
#pragma unroll
                for (int c = 0; c < 8; c++)
                    acc[i][c] = ffma2(x2, w2[c], acc[i][c]);
            }
        }
    }

    // epilogue
    float bv[8];
#pragma unroll
    for (int c = 0; c < 8; c++) bv[c] = args.bias[tc + 8 * c];
    float* out = args.out + (size_t)grp * NN * DD;
#pragma unroll
    for (int i = 0; i < 7; i++) {
        int r = row0 + tr * 7 + i;
        if (r >= NN) break;
#pragma unroll
        for (int c = 0; c < 8; c++) {
            float2 p = *(float2*)&acc[i][c];
            out[(size_t)r * DD + tc + 8 * c] = fmaxf(p.x + p.y + bv[c], 0.f);
        }
    }
}

// ---------------------------------------------------------------------------
// Launch
// ---------------------------------------------------------------------------
extern "C" void kernel_launch(void* const* d_in, const int* in_sizes, int n_in,
                              void* d_out, int out_size) {
    const float* x_drug = (const float*)d_in[0];
    const float* x_gene = (const float*)d_in[1];
    const float* W_dd   = (const float*)d_in[2];
    const float* W_dg   = (const float*)d_in[3];
    const float* W_gd   = (const float*)d_in[4];
    const float* W_gg   = (const float*)d_in[5];
    const float* bias   = (const float*)d_in[6];
    const int* src_dd = (const int*)d_in[7];
    const int* dst_dd = (const int*)d_in[8];
    const int* src_dg = (const int*)d_in[9];
    const int* dst_dg = (const int*)d_in[10];
    const int* src_gd = (const int*)d_in[11];
    const int* dst_gd = (const int*)d_in[12];
    const int* src_gg = (const int*)d_in[13];
    const int* dst_gg = (const int*)d_in[14];
    float* out = (float*)d_out;    // [2, N, D]: out[0]=drug, out[1]=gene

    EdgeArgs ea;
    ea.src[0] = src_dd; ea.dst[0] = dst_dd;
    ea.src[1] = src_gd; ea.dst[1] = dst_gd;
    ea.src[2] = src_gg; ea.dst[2] = dst_gg;
    ea.src[3] = src_dg; ea.dst[3] = dst_dg;

    // 1) zero degrees
    zero_deg_kernel<<<(NB / 4 + 255) / 256, 256>>>();

    // 2) degree count (all rels)
    {
        dim3 grid((EE + 255) / 256, 4);
        count_kernel<<<grid, 256>>>(ea, EE);
    }

    // 3-5) prefix scan of 400k bucket counts
    scan1_kernel<<<SCAN_BLKS, 512>>>();
    scan2_kernel<<<1, 512>>>();
    scan3_kernel<<<SCAN_BLKS, 512>>>();

    // 6) place edges into buckets
    {
        dim3 grid((EE + 255) / 256, 4);
        place_kernel<<<grid, 256>>>(ea, EE);
    }

    // 7) gather-aggregate (all rels; hot set = two 25.6MB x tables, L2-resident)
    {
        GatherArgs ga;
        ga.X[0] = x_drug; ga.X[1] = x_gene; ga.X[2] = x_gene; ga.X[3] = x_drug;
        dim3 grid((NN + 7) / 8, 4);   // (12500, 4)
        gather_kernel<<<grid, 256>>>(ga);
    }

    // 8) fused projection + bias + relu
    {
        ProjArgs args;
        args.W[0] = W_dd; args.W[1] = W_gd; args.W[2] = W_gg; args.W[3] = W_dg;
        args.bias = bias; args.out = out;
        dim3 grid((NN + BM - 1) / BM, 2);   // (893, 2)
        proj_fused_kernel<<<grid, 128>>>(args);
    }
}

// round 9
// speedup vs baseline: 2.4732x; 1.0202x over previous
#include <cuda_runtime.h>
#include <cuda_bf16.h>
#include <cstdint>

#define NN 100000
#define DD 64
#define EE 800000
#define BM 112
#define NB 400000            // total buckets = 4 rels * NN
#define SCAN_BLKS 391        // ceil(400000 / 1024), 1024 elems per block

// Scratch (static device globals — allocation-free per harness rules)
// rel 0: dd (dst=drug, src x_drug), 1: gd (dst=drug, src x_gene),
//     2: gg (dst=gene, src x_gene), 3: dg (dst=gene, src x_drug)
__device__ float g_agg[4][(size_t)NN * DD];   // pre-scaled aggregation per relation
__device__ int   g_deg[NB];                   // per-bucket in-degree
__device__ int   g_start[NB];                 // exclusive-scan bucket starts
__device__ int   g_cur[NB];                   // placement cursors
__device__ int   g_eidx[4 * EE];              // src node id per edge, bucketed by dst
__device__ int   g_bsum[512];                 // scan block sums (padded)

__device__ __forceinline__ unsigned long long ffma2(unsigned long long a,
                                                    unsigned long long b,
                                                    unsigned long long c) {
    unsigned long long d;
    asm("fma.rn.f32x2 %0, %1, %2, %3;" : "=l"(d) : "l"(a), "l"(b), "l"(c));
    return d;
}

// ---------------------------------------------------------------------------
// 1) zero degree counters
// ---------------------------------------------------------------------------
__global__ __launch_bounds__(256) void zero_deg_kernel() {
    int i = blockIdx.x * blockDim.x + threadIdx.x;
    if (i < NB / 4) ((int4*)g_deg)[i] = make_int4(0, 0, 0, 0);
}

// ---------------------------------------------------------------------------
// 2) degree count, all relations (grid.y = rel)
// ---------------------------------------------------------------------------
struct EdgeArgs { const int* src[4]; const int* dst[4]; };

__global__ __launch_bounds__(256) void count_kernel(EdgeArgs a, int e_cnt) {
    int rel = blockIdx.y;
    int e = blockIdx.x * blockDim.x + threadIdx.x;
    if (e < e_cnt) atomicAdd(&g_deg[rel * NN + a.dst[rel][e]], 1);
}

// ---------------------------------------------------------------------------
// 3) scan phase 1: 512 threads, 2 elements each (1024 per block).
//    Per-thread pair-sum -> Hillis-Steele over 512 -> expand to low/high.
//    Writes local-exclusive prefix to g_start, block total to g_bsum.
// ---------------------------------------------------------------------------
__global__ __launch_bounds__(512) void scan1_kernel() {
    __shared__ int buf[2][512];
    int tid = threadIdx.x;
    int base = blockIdx.x * 1024 + tid * 2;
    int v0 = (base < NB) ? g_deg[base] : 0;
    int v1 = (base + 1 < NB) ? g_deg[base + 1] : 0;
    int pair = v0 + v1;
    buf[0][tid] = pair;
    __syncthreads();
    int pa = 0;
    for (int off = 1; off < 512; off <<= 1) {
        int t = buf[pa][tid];
        if (tid >= off) t += buf[pa][tid - off];
        buf[pa ^ 1][tid] = t;
        __syncthreads();
        pa ^= 1;
    }
    int incl_pair = buf[pa][tid];          // inclusive over pair-sums
    int excl_pair = incl_pair - pair;      // exclusive over pair-sums
    if (base < NB)     g_start[base]     = excl_pair;
    if (base + 1 < NB) g_start[base + 1] = excl_pair + v0;
    if (tid == 511) g_bsum[blockIdx.x] = incl_pair;
}

// ---------------------------------------------------------------------------
// 4) scan phase 2+3 merged: each block reduces g_bsum[0..blockIdx.x) itself
//    (<=391 ints via L2), then applies the offset and inits cursors.
// ---------------------------------------------------------------------------
__global__ __launch_bounds__(512) void scan23_kernel() {
    __shared__ int red[16];
    __shared__ int s_off;
    int tid = threadIdx.x;

    int partial = 0;
    for (int i = tid; i < blockIdx.x; i += 512) partial += g_bsum[i];
#pragma unroll
    for (int o = 16; o > 0; o >>= 1)
        partial += __shfl_down_sync(0xffffffffu, partial, o);
    if ((tid & 31) == 0) red[tid >> 5] = partial;
    __syncthreads();
    if (tid < 16) {
        int v = red[tid];
#pragma unroll
        for (int o = 8; o > 0; o >>= 1)
            v += __shfl_down_sync(0x0000ffffu, v, o);
        if (tid == 0) s_off = v;
    }
    __syncthreads();
    int off = s_off;

    int base = blockIdx.x * 1024 + tid * 2;
#pragma unroll
    for (int u = 0; u < 2; u++) {
        int i = base + u;
        if (i < NB) {
            int v = g_start[i] + off;
            g_start[i] = v;
            g_cur[i] = v;
        }
    }
}

// ---------------------------------------------------------------------------
// 5) place src ids into dst buckets (grid.y = rel)
// ---------------------------------------------------------------------------
__global__ __launch_bounds__(256) void place_kernel(EdgeArgs a, int e_cnt) {
    int rel = blockIdx.y;
    int e = blockIdx.x * blockDim.x + threadIdx.x;
    if (e >= e_cnt) return;
    int s = a.src[rel][e];
    int d = a.dst[rel][e];
    int pos = atomicAdd(&g_cur[rel * NN + d], 1);
    g_eidx[pos] = s;
}

// ---------------------------------------------------------------------------
// 6) gather-aggregate: one warp per (rel, dst node). No atomics, single write.
//    g_agg[rel][node] = (1/max(deg,1)) * sum_{src in bucket} x[src]
//    8-wide unrolled main loop: 8 independent LDG.64 in flight, dual accums.
// ---------------------------------------------------------------------------
struct GatherArgs { const float* X[4]; };

__global__ __launch_bounds__(256) void gather_kernel(GatherArgs ga) {
    int rel = blockIdx.y;
    int node = blockIdx.x * 8 + (threadIdx.x >> 5);   // 8 warps per block
    if (node >= NN) return;
    int lane = threadIdx.x & 31;

    int b = rel * NN + node;
    int start = g_start[b];
    int cnt = g_deg[b];

    const float2* __restrict__ X2 = (const float2*)ga.X[rel];
    float2 accA = make_float2(0.f, 0.f);
    float2 accB = make_float2(0.f, 0.f);

    int j = 0;
    for (; j + 8 <= cnt; j += 8) {
        int id = (lane < 8) ? g_eidx[start + j + lane] : 0;
        int s0 = __shfl_sync(0xffffffffu, id, 0);
        int s1 = __shfl_sync(0xffffffffu, id, 1);
        int s2 = __shfl_sync(0xffffffffu, id, 2);
        int s3 = __shfl_sync(0xffffffffu, id, 3);
        int s4 = __shfl_sync(0xffffffffu, id, 4);
        int s5 = __shfl_sync(0xffffffffu, id, 5);
        int s6 = __shfl_sync(0xffffffffu, id, 6);
        int s7 = __shfl_sync(0xffffffffu, id, 7);
        float2 a0 = X2[(size_t)s0 * 32 + lane];
        float2 a1 = X2[(size_t)s1 * 32 + lane];
        float2 a2 = X2[(size_t)s2 * 32 + lane];
        float2 a3 = X2[(size_t)s3 * 32 + lane];
        float2 a4 = X2[(size_t)s4 * 32 + lane];
        float2 a5 = X2[(size_t)s5 * 32 + lane];
        float2 a6 = X2[(size_t)s6 * 32 + lane];
        float2 a7 = X2[(size_t)s7 * 32 + lane];
        accA.x += (a0.x + a1.x) + (a2.x + a3.x);
        accA.y += (a0.y + a1.y) + (a2.y + a3.y);
        accB.x += (a4.x + a5.x) + (a6.x + a7.x);
        accB.y += (a4.y + a5.y) + (a6.y + a7.y);
    }
    for (; j + 4 <= cnt; j += 4) {
        int id = (lane < 4) ? g_eidx[start + j + lane] : 0;
        int s0 = __shfl_sync(0xffffffffu, id, 0);
        int s1 = __shfl_sync(0xffffffffu, id, 1);
        int s2 = __shfl_sync(0xffffffffu, id, 2);
        int s3 = __shfl_sync(0xffffffffu, id, 3);
        float2 a0 = X2[(size_t)s0 * 32 + lane];
        float2 a1 = X2[(size_t)s1 * 32 + lane];
        float2 a2 = X2[(size_t)s2 * 32 + lane];
        float2 a3 = X2[(size_t)s3 * 32 + lane];
        accA.x += (a0.x + a1.x) + (a2.x + a3.x);
        accA.y += (a0.y + a1.y) + (a2.y + a3.y);
    }
    for (; j < cnt; j++) {
        int s = g_eidx[start + j];           // uniform address -> broadcast
        float2 a0 = X2[(size_t)s * 32 + lane];
        accB.x += a0.x;
        accB.y += a0.y;
    }

    float inv = 1.0f / (float)(cnt > 1 ? cnt : 1);
    float2 acc;
    acc.x = (accA.x + accB.x) * inv;
    acc.y = (accA.y + accB.y) * inv;
    ((float2*)g_agg[rel])[(size_t)node * 32 + lane] = acc;
}

// ---------------------------------------------------------------------------
// 7) fused projection: out[type] = relu(agg_r0 @ W_r0 + agg_r1 @ W_r1 + bias)
//    grid.y = dst type. 128 threads, block tile 112x64, thread tile 7x8
//    (cols tc + 8*c). Conflict-free pair-layout smem [..][33].
// ---------------------------------------------------------------------------
struct ProjArgs { const float* W[4]; const float* bias; float* out; };

__global__ __launch_bounds__(128, 2) void proj_fused_kernel(ProjArgs args) {
    __shared__ float2 Xs[BM][33];    // Xs[m][k2] = (x[m][2k2], x[m][2k2+1])
    __shared__ float2 Wt[DD][33];    // Wt[n][k2] = (W[2k2][n], W[2k2+1][n])

    int tid = threadIdx.x;
    int tc = tid & 7;                // output cols: tc + 8*c, c in 0..7
    int tr = tid >> 3;               // rows: tr*7 .. tr*7+6 (tr in 0..15)
    int row0 = blockIdx.x * BM;
    int grp = blockIdx.y;            // 0 = drug, 1 = gene

    unsigned long long acc[7][8];
#pragma unroll
    for (int i = 0; i < 7; i++)
#pragma unroll
        for (int c = 0; c < 8; c++) acc[i][c] = 0ull;

#pragma unroll
    for (int chunk = 0; chunk < 2; chunk++) {
        int rel = grp * 2 + chunk;
        const float4* __restrict__ agg4 = (const float4*)g_agg[rel];
        const float4* __restrict__ W4 = (const float4*)args.W[rel];

        __syncthreads();   // protect previous chunk's smem reads

        // load X tile: 112 rows x 16 float4 = 1792 float4, 128 threads
#pragma unroll
        for (int j = 0; j < 14; j++) {
            int idx = tid + j * 128;
            int m = idx >> 4;
            int q = idx & 15;
            int r = row0 + m;
            float4 v = make_float4(0.f, 0.f, 0.f, 0.f);
            if (r < NN) v = agg4[(size_t)r * 16 + q];
            Xs[m][q * 2]     = make_float2(v.x, v.y);
            Xs[m][q * 2 + 1] = make_float2(v.z, v.w);
        }
        // load W transposed into pair layout
#pragma unroll
        for (int j = 0; j < 8; j++) {
            int idx = tid + j * 128;       // float4 index over 1024
            int k = idx >> 4;
            int n4 = (idx & 15) * 4;
            float4 w = W4[idx];
            float* wt = (float*)&Wt[0][0];
            int base = (k >> 1) * 2 + (k & 1);
            wt[(n4 + 0) * 66 + base] = w.x;
            wt[(n4 + 1) * 66 + base] = w.y;
            wt[(n4 + 2) * 66 + base] = w.z;
            wt[(n4 + 3) * 66 + base] = w.w;
        }
        __syncthreads();

        const unsigned long long* xrow =
            (const unsigned long long*)&Xs[tr * 7][0];
        const unsigned long long* wbase = (const unsigned long long*)&Wt[0][0];
#pragma unroll 4
        for (int k2 = 0; k2 < 32; k2++) {
            unsigned long long w2[8];
#pragma unroll
            for (int c = 0; c < 8; c++)
                w2[c] = wbase[(tc + 8 * c) * 33 + k2];
#pragma unroll
            for (int i = 0; i < 7; i++) {
                unsigned long long x2 = xrow[i * 33 + k2];
#pragma unroll
                for (int c = 0; c < 8; c++)
                    acc[i][c] = ffma2(x2, w2[c], acc[i][c]);
            }
        }
    }

    // epilogue
    float bv[8];
#pragma unroll
    for (int c = 0; c < 8; c++) bv[c] = args.bias[tc + 8 * c];
    float* out = args.out + (size_t)grp * NN * DD;
#pragma unroll
    for (int i = 0; i < 7; i++) {
        int r = row0 + tr * 7 + i;
        if (r >= NN) break;
#pragma unroll
        for (int c = 0; c < 8; c++) {
            float2 p = *(float2*)&acc[i][c];
            out[(size_t)r * DD + tc + 8 * c] = fmaxf(p.x + p.y + bv[c], 0.f);
        }
    }
}

// ---------------------------------------------------------------------------
// Launch
// ---------------------------------------------------------------------------
extern "C" void kernel_launch(void* const* d_in, const int* in_sizes, int n_in,
                              void* d_out, int out_size) {
    const float* x_drug = (const float*)d_in[0];
    const float* x_gene = (const float*)d_in[1];
    const float* W_dd   = (const float*)d_in[2];
    const float* W_dg   = (const float*)d_in[3];
    const float* W_gd   = (const float*)d_in[4];
    const float* W_gg   = (const float*)d_in[5];
    const float* bias   = (const float*)d_in[6];
    const int* src_dd = (const int*)d_in[7];
    const int* dst_dd = (const int*)d_in[8];
    const int* src_dg = (const int*)d_in[9];
    const int* dst_dg = (const int*)d_in[10];
    const int* src_gd = (const int*)d_in[11];
    const int* dst_gd = (const int*)d_in[12];
    const int* src_gg = (const int*)d_in[13];
    const int* dst_gg = (const int*)d_in[14];
    float* out = (float*)d_out;    // [2, N, D]: out[0]=drug, out[1]=gene

    EdgeArgs ea;
    ea.src[0] = src_dd; ea.dst[0] = dst_dd;
    ea.src[1] = src_gd; ea.dst[1] = dst_gd;
    ea.src[2] = src_gg; ea.dst[2] = dst_gg;
    ea.src[3] = src_dg; ea.dst[3] = dst_dg;

    // 1) zero degrees
    zero_deg_kernel<<<(NB / 4 + 255) / 256, 256>>>();

    // 2) degree count (all rels)
    {
        dim3 grid((EE + 255) / 256, 4);
        count_kernel<<<grid, 256>>>(ea, EE);
    }

    // 3-4) prefix scan of 400k bucket counts (2 kernels)
    scan1_kernel<<<SCAN_BLKS, 512>>>();
    scan23_kernel<<<SCAN_BLKS, 512>>>();

    // 5) place edges into buckets
    {
        dim3 grid((EE + 255) / 256, 4);
        place_kernel<<<grid, 256>>>(ea, EE);
    }

    // 6) gather-aggregate (all rels; hot set = two 25.6MB x tables, L2-resident)
    {
        GatherArgs ga;
        ga.X[0] = x_drug; ga.X[1] = x_gene; ga.X[2] = x_gene; ga.X[3] = x_drug;
        dim3 grid((NN + 7) / 8, 4);   // (12500, 4)
        gather_kernel<<<grid, 256>>>(ga);
    }

    // 7) fused projection + bias + relu
    {
        ProjArgs args;
        args.W[0] = W_dd; args.W[1] = W_gd; args.W[2] = W_gg; args.W[3] = W_dg;
        args.bias = bias; args.out = out;
        dim3 grid((NN + BM - 1) / BM, 2);   // (893, 2)
        proj_fused_kernel<<<grid, 128>>>(args);
    }
}